// round 2
// baseline (speedup 1.0000x reference)
#include <cuda_runtime.h>
#include <cuda_fp16.h>
#include <mma.h>

using namespace nvcuda;

#define NHEADS   8
#define DH       64
#define TSEQ     2048
#define BATCH    4
#define HIDDEN   256
#define DMODEL   (NHEADS * DH)      // 512
#define NTOK     (TSEQ * BATCH)     // 8192
#define SCALING  0.125f             // 64^-0.5

// ---------------- device scratch (static: no allocation allowed) ----------------
__device__ __half g_hid[NTOK * HIDDEN];                  // MLP hidden scratch (reused q/k/v)
__device__ __half g_q[BATCH * NHEADS * TSEQ * DH];       // [b,h,t,d] fp16 (pre-scaled)
__device__ __half g_k[BATCH * NHEADS * TSEQ * DH];
__device__ __half g_v[BATCH * NHEADS * TSEQ * DH];
__device__ __half g_ao[NTOK * DMODEL];                   // attention out, token-major [t*B+b][h*64+d]

// =====================================================================
// Stage 1: H = relu(X @ W1 + b1)   (M=8192, K=64, N=256), fp16 out
// =====================================================================
__global__ __launch_bounds__(128) void mlp1_kernel(const float* __restrict__ X,
                                                   const float* __restrict__ W,
                                                   const float* __restrict__ bias) {
    __shared__ __half Xs[64][72];
    __shared__ __half Ws[64][72];
    __shared__ float  Cs[64][68];
    const int tid = threadIdx.x;
    const int n0 = blockIdx.x * 64;
    const int m0 = blockIdx.y * 64;

    for (int i = tid; i < 64 * 64; i += 128) {
        int r = i >> 6, c = i & 63;
        Xs[r][c] = __float2half(X[(size_t)(m0 + r) * DH + c]);
        Ws[r][c] = __float2half(W[(size_t)r * HIDDEN + n0 + c]);
    }
    __syncthreads();

    const int w = tid >> 5, wy = w >> 1, wx = w & 1;
    wmma::fragment<wmma::accumulator, 16, 16, 16, float> acc[2][2];
    for (int i = 0; i < 2; i++) for (int j = 0; j < 2; j++) wmma::fill_fragment(acc[i][j], 0.0f);
    for (int k = 0; k < 4; k++) {
        wmma::fragment<wmma::matrix_a, 16, 16, 16, __half, wmma::row_major> a[2];
        for (int i = 0; i < 2; i++)
            wmma::load_matrix_sync(a[i], &Xs[wy * 32 + i * 16][k * 16], 72);
        for (int j = 0; j < 2; j++) {
            wmma::fragment<wmma::matrix_b, 16, 16, 16, __half, wmma::row_major> bf;
            wmma::load_matrix_sync(bf, &Ws[k * 16][wx * 32 + j * 16], 72);
            for (int i = 0; i < 2; i++) wmma::mma_sync(acc[i][j], a[i], bf, acc[i][j]);
        }
    }
    for (int i = 0; i < 2; i++)
        for (int j = 0; j < 2; j++)
            wmma::store_matrix_sync(&Cs[wy * 32 + i * 16][wx * 32 + j * 16], acc[i][j], 68, wmma::mem_row_major);
    __syncthreads();

    for (int i = tid; i < 64 * 64; i += 128) {
        int r = i >> 6, c = i & 63;
        float v = Cs[r][c] + bias[n0 + c];
        v = fmaxf(v, 0.0f);
        g_hid[(size_t)(m0 + r) * HIDDEN + n0 + c] = __float2half(v);
    }
}

// =====================================================================
// Stage 2: OUT = (H @ W2 + b2) * scale  -> permuted store into [b,h,seq,d]
// (M=8192, K=256, N=512). mode 0=q,1=k,2=v
// =====================================================================
__global__ __launch_bounds__(128) void mlp2_kernel(const float* __restrict__ W,
                                                   const float* __restrict__ bias,
                                                   float scale, int mode) {
    __shared__ __half Hs[64][72];
    __shared__ __half Ws[64][72];
    __shared__ float  Cs[64][68];
    const int tid = threadIdx.x;
    const int n0 = blockIdx.x * 64;
    const int m0 = blockIdx.y * 64;
    const int w = tid >> 5, wy = w >> 1, wx = w & 1;

    wmma::fragment<wmma::accumulator, 16, 16, 16, float> acc[2][2];
    for (int i = 0; i < 2; i++) for (int j = 0; j < 2; j++) wmma::fill_fragment(acc[i][j], 0.0f);

    for (int kc = 0; kc < HIDDEN / 64; kc++) {
        for (int i = tid; i < 64 * 64; i += 128) {
            int r = i >> 6, c = i & 63;
            Hs[r][c] = g_hid[(size_t)(m0 + r) * HIDDEN + kc * 64 + c];
            Ws[r][c] = __float2half(W[(size_t)(kc * 64 + r) * DMODEL + n0 + c]);
        }
        __syncthreads();
        for (int k = 0; k < 4; k++) {
            wmma::fragment<wmma::matrix_a, 16, 16, 16, __half, wmma::row_major> a[2];
            for (int i = 0; i < 2; i++)
                wmma::load_matrix_sync(a[i], &Hs[wy * 32 + i * 16][k * 16], 72);
            for (int j = 0; j < 2; j++) {
                wmma::fragment<wmma::matrix_b, 16, 16, 16, __half, wmma::row_major> bf;
                wmma::load_matrix_sync(bf, &Ws[k * 16][wx * 32 + j * 16], 72);
                for (int i = 0; i < 2; i++) wmma::mma_sync(acc[i][j], a[i], bf, acc[i][j]);
            }
        }
        __syncthreads();
    }
    for (int i = 0; i < 2; i++)
        for (int j = 0; j < 2; j++)
            wmma::store_matrix_sync(&Cs[wy * 32 + i * 16][wx * 32 + j * 16], acc[i][j], 68, wmma::mem_row_major);
    __syncthreads();

    __half* dst = (mode == 0) ? g_q : (mode == 1) ? g_k : g_v;
    for (int i = tid; i < 64 * 64; i += 128) {
        int r = i >> 6, cc = i & 63;
        int col = n0 + cc;
        float v = (Cs[r][cc] + bias[col]) * scale;
        int tok = m0 + r;
        int t = tok >> 2;          // token index / BATCH
        int b = tok & 3;
        int h = col >> 6;
        int d = col & 63;
        dst[(((size_t)(b * NHEADS + h)) * TSEQ + t) * DH + d] = __float2half(v);
    }
}

// =====================================================================
// Flash attention: one CTA per (h, t-tile(64), b). Online softmax.
// grid = (8, 32, 4); head fastest -> mask slab shared in L2 across heads.
// =====================================================================
#define ATTN_SMEM 72192

__global__ __launch_bounds__(128) void attn_kernel(const float* __restrict__ mask) {
    extern __shared__ char sm[];
    __half (*Qs)[72] = (__half(*)[72])(sm);
    __half (*Ks)[72] = (__half(*)[72])(sm + 9216);
    __half (*Vs)[72] = (__half(*)[72])(sm + 18432);
    __half (*Ps)[72] = (__half(*)[72])(sm + 27648);
    float  (*Ss)[68] = (float (*)[68])(sm + 36864);
    float  (*Os)[68] = (float (*)[68])(sm + 54272);
    float* sm_m = (float*)(sm + 71680);
    float* sm_l = (float*)(sm + 71936);

    const int tid = threadIdx.x;
    const int h = blockIdx.x;
    const int t0 = blockIdx.y * 64;
    const int b = blockIdx.z;
    const int w = tid >> 5;

    const __half* qbase = g_q + ((size_t)(b * NHEADS + h) * TSEQ + t0) * DH;
    const __half* kbase = g_k + (size_t)(b * NHEADS + h) * TSEQ * DH;
    const __half* vbase = g_v + (size_t)(b * NHEADS + h) * TSEQ * DH;

    // load Q tile (64x64 halves) as uint4
    {
        const uint4* qg = (const uint4*)qbase;
        for (int i = tid; i < 64 * 8; i += 128) {
            int r = i >> 3, c = i & 7;
            ((uint4*)&Qs[r][0])[c] = qg[r * 8 + c];
        }
    }
    for (int i = tid; i < 64 * 64; i += 128) {
        int r = i >> 6, c = i & 63;
        Os[r][c] = 0.0f;
    }
    if (tid < 64) { sm_m[tid] = -1e30f; sm_l[tid] = 0.0f; }
    __syncthreads();

    for (int s0 = 0; s0 < TSEQ; s0 += 64) {
        // load K, V chunk
        {
            const uint4* kg = (const uint4*)(kbase + (size_t)s0 * DH);
            const uint4* vg = (const uint4*)(vbase + (size_t)s0 * DH);
            for (int i = tid; i < 64 * 8; i += 128) {
                int r = i >> 3, c = i & 7;
                ((uint4*)&Ks[r][0])[c] = kg[r * 8 + c];
                ((uint4*)&Vs[r][0])[c] = vg[r * 8 + c];
            }
        }
        __syncthreads();

        // S = Q @ K^T  (each warp: 16-row strip x 64 cols)
        {
            wmma::fragment<wmma::accumulator, 16, 16, 16, float> acc[4];
            for (int j = 0; j < 4; j++) wmma::fill_fragment(acc[j], 0.0f);
            for (int k = 0; k < 4; k++) {
                wmma::fragment<wmma::matrix_a, 16, 16, 16, __half, wmma::row_major> a;
                wmma::load_matrix_sync(a, &Qs[w * 16][k * 16], 72);
                for (int j = 0; j < 4; j++) {
                    wmma::fragment<wmma::matrix_b, 16, 16, 16, __half, wmma::col_major> bf;
                    wmma::load_matrix_sync(bf, &Ks[j * 16][k * 16], 72);
                    wmma::mma_sync(acc[j], a, bf, acc[j]);
                }
            }
            for (int j = 0; j < 4; j++)
                wmma::store_matrix_sync(&Ss[w * 16][j * 16], acc[j], 68, wmma::mem_row_major);
        }
        __syncthreads();

        // online softmax (2 threads per row)
        {
            const int r = tid >> 1, part = tid & 1;
            const float* mk = mask + ((size_t)b * TSEQ + (t0 + r)) * TSEQ + s0 + part * 32;
            float* sr = &Ss[r][part * 32];
            float mx = -1e30f;
            #pragma unroll 8
            for (int j = 0; j < 32; j++) {
                float s = sr[j] + mk[j];
                sr[j] = s;
                mx = fmaxf(mx, s);
            }
            mx = fmaxf(mx, __shfl_xor_sync(0xffffffffu, mx, 1));
            float mo = sm_m[r];
            float mn = fmaxf(mo, mx);
            float alpha = __expf(mo - mn);
            float sum = 0.0f;
            __half* pr = &Ps[r][part * 32];
            #pragma unroll 8
            for (int j = 0; j < 32; j++) {
                float p = __expf(sr[j] - mn);
                pr[j] = __float2half(p);
                sum += p;
            }
            sum += __shfl_xor_sync(0xffffffffu, sum, 1);
            float* orow = &Os[r][part * 32];
            #pragma unroll 8
            for (int j = 0; j < 32; j++) orow[j] *= alpha;
            if (part == 0) { sm_m[r] = mn; sm_l[r] = sm_l[r] * alpha + sum; }
        }
        __syncthreads();

        // O += P @ V
        {
            wmma::fragment<wmma::accumulator, 16, 16, 16, float> acc[4];
            for (int j = 0; j < 4; j++)
                wmma::load_matrix_sync(acc[j], &Os[w * 16][j * 16], 68, wmma::mem_row_major);
            for (int k = 0; k < 4; k++) {
                wmma::fragment<wmma::matrix_a, 16, 16, 16, __half, wmma::row_major> a;
                wmma::load_matrix_sync(a, &Ps[w * 16][k * 16], 72);
                for (int j = 0; j < 4; j++) {
                    wmma::fragment<wmma::matrix_b, 16, 16, 16, __half, wmma::row_major> bf;
                    wmma::load_matrix_sync(bf, &Vs[k * 16][j * 16], 72);
                    wmma::mma_sync(acc[j], a, bf, acc[j]);
                }
            }
            for (int j = 0; j < 4; j++)
                wmma::store_matrix_sync(&Os[w * 16][j * 16], acc[j], 68, wmma::mem_row_major);
        }
        __syncthreads();
    }

    // normalize and write out: AO[(t*B+b)][h*64+d]
    for (int i = tid; i < 64 * 64; i += 128) {
        int r = i >> 6, d = i & 63;
        float v = Os[r][d] / sm_l[r];
        size_t tok = (size_t)(t0 + r) * BATCH + b;
        g_ao[tok * DMODEL + h * DH + d] = __float2half(v);
    }
}

// =====================================================================
// Output projection: OUT[8192,64] = AO[8192,512] @ Wo + bo  (fp32 out)
// =====================================================================
__global__ __launch_bounds__(128) void oproj_kernel(const float* __restrict__ W,
                                                    const float* __restrict__ bias,
                                                    float* __restrict__ out) {
    __shared__ __half As[64][72];
    __shared__ __half Ws[64][72];
    __shared__ float  Cs[64][68];
    const int tid = threadIdx.x;
    const int m0 = blockIdx.x * 64;
    const int w = tid >> 5, wy = w >> 1, wx = w & 1;

    wmma::fragment<wmma::accumulator, 16, 16, 16, float> acc[2][2];
    for (int i = 0; i < 2; i++) for (int j = 0; j < 2; j++) wmma::fill_fragment(acc[i][j], 0.0f);

    for (int kc = 0; kc < DMODEL / 64; kc++) {
        for (int i = tid; i < 64 * 64; i += 128) {
            int r = i >> 6, c = i & 63;
            As[r][c] = g_ao[(size_t)(m0 + r) * DMODEL + kc * 64 + c];
            Ws[r][c] = __float2half(W[(size_t)(kc * 64 + r) * DH + c]);
        }
        __syncthreads();
        for (int k = 0; k < 4; k++) {
            wmma::fragment<wmma::matrix_a, 16, 16, 16, __half, wmma::row_major> a[2];
            for (int i = 0; i < 2; i++)
                wmma::load_matrix_sync(a[i], &As[wy * 32 + i * 16][k * 16], 72);
            for (int j = 0; j < 2; j++) {
                wmma::fragment<wmma::matrix_b, 16, 16, 16, __half, wmma::row_major> bf;
                wmma::load_matrix_sync(bf, &Ws[k * 16][wx * 32 + j * 16], 72);
                for (int i = 0; i < 2; i++) wmma::mma_sync(acc[i][j], a[i], bf, acc[i][j]);
            }
        }
        __syncthreads();
    }
    for (int i = 0; i < 2; i++)
        for (int j = 0; j < 2; j++)
            wmma::store_matrix_sync(&Cs[wy * 32 + i * 16][wx * 32 + j * 16], acc[i][j], 68, wmma::mem_row_major);
    __syncthreads();

    for (int i = tid; i < 64 * 64; i += 128) {
        int r = i >> 6, c = i & 63;
        out[(size_t)(m0 + r) * DH + c] = Cs[r][c] + bias[c];
    }
}

// =====================================================================
extern "C" void kernel_launch(void* const* d_in, const int* in_sizes, int n_in,
                              void* d_out, int out_size) {
    const float* query = (const float*)d_in[0];
    const float* key   = (const float*)d_in[1];
    const float* value = (const float*)d_in[2];
    const float* amask = (const float*)d_in[3];
    const float* Wq1 = (const float*)d_in[4];
    const float* bq1 = (const float*)d_in[5];
    const float* Wq2 = (const float*)d_in[6];
    const float* bq2 = (const float*)d_in[7];
    const float* Wk1 = (const float*)d_in[8];
    const float* bk1 = (const float*)d_in[9];
    const float* Wk2 = (const float*)d_in[10];
    const float* bk2 = (const float*)d_in[11];
    const float* Wv1 = (const float*)d_in[12];
    const float* bv1 = (const float*)d_in[13];
    const float* Wv2 = (const float*)d_in[14];
    const float* bv2 = (const float*)d_in[15];
    const float* Wo  = (const float*)d_in[16];
    const float* bo  = (const float*)d_in[17];
    float* out = (float*)d_out;

    dim3 blk(128);
    dim3 g1(HIDDEN / 64, NTOK / 64);
    dim3 g2(DMODEL / 64, NTOK / 64);

    // q
    mlp1_kernel<<<g1, blk>>>(query, Wq1, bq1);
    mlp2_kernel<<<g2, blk>>>(Wq2, bq2, SCALING, 0);
    // k
    mlp1_kernel<<<g1, blk>>>(key, Wk1, bk1);
    mlp2_kernel<<<g2, blk>>>(Wk2, bk2, 1.0f, 1);
    // v
    mlp1_kernel<<<g1, blk>>>(value, Wv1, bv1);
    mlp2_kernel<<<g2, blk>>>(Wv2, bv2, 1.0f, 2);

    // attention (head fastest in grid for L2 mask reuse)
    cudaFuncSetAttribute(attn_kernel, cudaFuncAttributeMaxDynamicSharedMemorySize, ATTN_SMEM);
    attn_kernel<<<dim3(NHEADS, TSEQ / 64, BATCH), blk, ATTN_SMEM>>>(amask);

    // output projection
    oproj_kernel<<<dim3(NTOK / 64), blk>>>(Wo, bo, out);
}

// round 4
// speedup vs baseline: 4.3361x; 4.3361x over previous
#include <cuda_runtime.h>
#include <cuda_fp16.h>
#include <mma.h>
#include <cstdint>

using namespace nvcuda;

#define NHEADS   8
#define DH       64
#define TSEQ     2048
#define BATCH    4
#define HIDDEN   256
#define DMODEL   (NHEADS * DH)      // 512
#define NTOK     (TSEQ * BATCH)     // 8192
#define SCALING  0.125f
#define LOG2E    1.4426950408889634f

// ---------------- device scratch ----------------
__device__ __half g_hid[3][NTOK * HIDDEN];
__device__ __half g_q[BATCH * NHEADS * TSEQ * DH];   // [b,h,t,d], q pre-scaled
__device__ __half g_k[BATCH * NHEADS * TSEQ * DH];
__device__ __half g_v[BATCH * NHEADS * TSEQ * DH];
__device__ __half g_ao[NTOK * DMODEL];               // [t*B+b][h*64+d]

// ======================= PTX helpers =======================
__device__ __forceinline__ void ldsm4(uint32_t& r0, uint32_t& r1, uint32_t& r2, uint32_t& r3, const void* p) {
    uint32_t a = (uint32_t)__cvta_generic_to_shared(p);
    asm volatile("ldmatrix.sync.aligned.m8n8.x4.shared.b16 {%0,%1,%2,%3}, [%4];"
                 : "=r"(r0), "=r"(r1), "=r"(r2), "=r"(r3) : "r"(a));
}
__device__ __forceinline__ void ldsm4t(uint32_t& r0, uint32_t& r1, uint32_t& r2, uint32_t& r3, const void* p) {
    uint32_t a = (uint32_t)__cvta_generic_to_shared(p);
    asm volatile("ldmatrix.sync.aligned.m8n8.x4.trans.shared.b16 {%0,%1,%2,%3}, [%4];"
                 : "=r"(r0), "=r"(r1), "=r"(r2), "=r"(r3) : "r"(a));
}
__device__ __forceinline__ void mma16816(float* c, const uint32_t* a, uint32_t b0, uint32_t b1) {
    asm volatile("mma.sync.aligned.m16n8k16.row.col.f32.f16.f16.f32 "
                 "{%0,%1,%2,%3}, {%4,%5,%6,%7}, {%8,%9}, {%0,%1,%2,%3};"
                 : "+f"(c[0]), "+f"(c[1]), "+f"(c[2]), "+f"(c[3])
                 : "r"(a[0]), "r"(a[1]), "r"(a[2]), "r"(a[3]), "r"(b0), "r"(b1));
}
__device__ __forceinline__ float ex2(float x) {
    float r; asm("ex2.approx.ftz.f32 %0, %1;" : "=f"(r) : "f"(x)); return r;
}
__device__ __forceinline__ void cpa16(void* dst, const void* src) {
    asm volatile("cp.async.cg.shared.global [%0], [%1], 16;"
                 :: "r"((uint32_t)__cvta_generic_to_shared(dst)), "l"(src));
}
__device__ __forceinline__ uint32_t h2u(__half2 v) {
    return *reinterpret_cast<uint32_t*>(&v);
}

// =====================================================================
// Stage 1 (merged q/k/v): H = relu(X @ W1 + b1)
// =====================================================================
__global__ __launch_bounds__(128) void mlp1_kernel(
        const float* __restrict__ Xq, const float* __restrict__ Xk, const float* __restrict__ Xv,
        const float* __restrict__ Wq, const float* __restrict__ Wk, const float* __restrict__ Wv,
        const float* __restrict__ bq, const float* __restrict__ bk, const float* __restrict__ bv) {
    __shared__ __half Xs[64][72];
    __shared__ __half Ws[64][72];
    __shared__ float  Cs[64][68];
    const int tid = threadIdx.x;
    const int n0 = blockIdx.x * 64;
    const int m0 = blockIdx.y * 64;
    const int z  = blockIdx.z;
    const float* X = (z == 0) ? Xq : (z == 1) ? Xk : Xv;
    const float* W = (z == 0) ? Wq : (z == 1) ? Wk : Wv;
    const float* bias = (z == 0) ? bq : (z == 1) ? bk : bv;

    for (int i = tid; i < 64 * 64; i += 128) {
        int r = i >> 6, c = i & 63;
        Xs[r][c] = __float2half(X[(size_t)(m0 + r) * DH + c]);
        Ws[r][c] = __float2half(W[(size_t)r * HIDDEN + n0 + c]);
    }
    __syncthreads();

    const int w = tid >> 5, wy = w >> 1, wx = w & 1;
    wmma::fragment<wmma::accumulator, 16, 16, 16, float> acc[2][2];
    for (int i = 0; i < 2; i++) for (int j = 0; j < 2; j++) wmma::fill_fragment(acc[i][j], 0.0f);
    for (int k = 0; k < 4; k++) {
        wmma::fragment<wmma::matrix_a, 16, 16, 16, __half, wmma::row_major> a[2];
        for (int i = 0; i < 2; i++)
            wmma::load_matrix_sync(a[i], &Xs[wy * 32 + i * 16][k * 16], 72);
        for (int j = 0; j < 2; j++) {
            wmma::fragment<wmma::matrix_b, 16, 16, 16, __half, wmma::row_major> bf;
            wmma::load_matrix_sync(bf, &Ws[k * 16][wx * 32 + j * 16], 72);
            for (int i = 0; i < 2; i++) wmma::mma_sync(acc[i][j], a[i], bf, acc[i][j]);
        }
    }
    for (int i = 0; i < 2; i++)
        for (int j = 0; j < 2; j++)
            wmma::store_matrix_sync(&Cs[wy * 32 + i * 16][wx * 32 + j * 16], acc[i][j], 68, wmma::mem_row_major);
    __syncthreads();

    for (int i = tid; i < 64 * 64; i += 128) {
        int r = i >> 6, c = i & 63;
        float v = fmaxf(Cs[r][c] + bias[n0 + c], 0.0f);
        g_hid[z][(size_t)(m0 + r) * HIDDEN + n0 + c] = __float2half(v);
    }
}

// =====================================================================
// Stage 2 (merged): OUT = (H @ W2 + b2) * scale -> [b,h,t,d]
// =====================================================================
__global__ __launch_bounds__(128) void mlp2_kernel(
        const float* __restrict__ Wq, const float* __restrict__ Wk, const float* __restrict__ Wv,
        const float* __restrict__ bq, const float* __restrict__ bk, const float* __restrict__ bv) {
    __shared__ __half Hs[64][72];
    __shared__ __half Ws[64][72];
    __shared__ float  Cs[64][68];
    const int tid = threadIdx.x;
    const int n0 = blockIdx.x * 64;
    const int m0 = blockIdx.y * 64;
    const int z  = blockIdx.z;
    const float* W = (z == 0) ? Wq : (z == 1) ? Wk : Wv;
    const float* bias = (z == 0) ? bq : (z == 1) ? bk : bv;
    const float scale = (z == 0) ? SCALING : 1.0f;
    const int w = tid >> 5, wy = w >> 1, wx = w & 1;

    wmma::fragment<wmma::accumulator, 16, 16, 16, float> acc[2][2];
    for (int i = 0; i < 2; i++) for (int j = 0; j < 2; j++) wmma::fill_fragment(acc[i][j], 0.0f);

    for (int kc = 0; kc < HIDDEN / 64; kc++) {
        for (int i = tid; i < 64 * 64; i += 128) {
            int r = i >> 6, c = i & 63;
            Hs[r][c] = g_hid[z][(size_t)(m0 + r) * HIDDEN + kc * 64 + c];
            Ws[r][c] = __float2half(W[(size_t)(kc * 64 + r) * DMODEL + n0 + c]);
        }
        __syncthreads();
        for (int k = 0; k < 4; k++) {
            wmma::fragment<wmma::matrix_a, 16, 16, 16, __half, wmma::row_major> a[2];
            for (int i = 0; i < 2; i++)
                wmma::load_matrix_sync(a[i], &Hs[wy * 32 + i * 16][k * 16], 72);
            for (int j = 0; j < 2; j++) {
                wmma::fragment<wmma::matrix_b, 16, 16, 16, __half, wmma::row_major> bf;
                wmma::load_matrix_sync(bf, &Ws[k * 16][wx * 32 + j * 16], 72);
                for (int i = 0; i < 2; i++) wmma::mma_sync(acc[i][j], a[i], bf, acc[i][j]);
            }
        }
        __syncthreads();
    }
    for (int i = 0; i < 2; i++)
        for (int j = 0; j < 2; j++)
            wmma::store_matrix_sync(&Cs[wy * 32 + i * 16][wx * 32 + j * 16], acc[i][j], 68, wmma::mem_row_major);
    __syncthreads();

    __half* dst = (z == 0) ? g_q : (z == 1) ? g_k : g_v;
    for (int i = tid; i < 64 * 64; i += 128) {
        int r = i >> 6, cc = i & 63;
        int col = n0 + cc;
        float v = (Cs[r][cc] + bias[col]) * scale;
        int tok = m0 + r;
        int t = tok >> 2, b = tok & 3;
        int h = col >> 6, d = col & 63;
        dst[(((size_t)(b * NHEADS + h)) * TSEQ + t) * DH + d] = __float2half(v);
    }
}

// =====================================================================
// Flash attention, FA2 register pipeline.
// CTA: 128 thr (4 warps), Br=64 (16 rows/warp), Bc=64, D=64.
// grid = (8 heads, 32 t-tiles, 4 batch); head fastest for L2 mask reuse.
// =====================================================================
__global__ __launch_bounds__(128, 3) void attn_kernel(const float* __restrict__ mask) {
    __shared__ __half Qs[64][72];
    __shared__ __half Ks[2][64][72];
    __shared__ __half Vs[2][64][72];

    const int tid  = threadIdx.x;
    const int lane = tid & 31;
    const int w    = tid >> 5;
    const int h    = blockIdx.x;
    const int t0   = blockIdx.y * 64;
    const int b    = blockIdx.z;

    const __half* qbase = g_q + ((size_t)(b * NHEADS + h) * TSEQ + t0) * DH;
    const __half* kbase = g_k + (size_t)(b * NHEADS + h) * TSEQ * DH;
    const __half* vbase = g_v + (size_t)(b * NHEADS + h) * TSEQ * DH;

    // Q tile 64x64 -> smem (plain vector loads)
    for (int i = tid; i < 64 * 8; i += 128) {
        int r = i >> 3, c = i & 7;
        *(uint4*)&Qs[r][c * 8] = ((const uint4*)qbase)[i];
    }
    // prologue: K/V stage 0 via cp.async
    for (int i = tid; i < 512; i += 128) {
        int r = i >> 3, c = i & 7;
        cpa16(&Ks[0][r][c * 8], kbase + r * 64 + c * 8);
        cpa16(&Vs[0][r][c * 8], vbase + r * 64 + c * 8);
    }
    asm volatile("cp.async.commit_group;");
    __syncthreads();   // Qs visible

    // Q fragments (resident): 4 k-steps
    uint32_t qa[4][4];
    #pragma unroll
    for (int kk = 0; kk < 4; kk++)
        ldsm4(qa[kk][0], qa[kk][1], qa[kk][2], qa[kk][3],
              &Qs[w * 16 + (lane & 15)][kk * 16 + 8 * (lane >> 4)]);

    float Oa[8][4];
    #pragma unroll
    for (int j = 0; j < 8; j++) { Oa[j][0] = Oa[j][1] = Oa[j][2] = Oa[j][3] = 0.0f; }
    float m0 = -1e30f, m1 = -1e30f, l0 = 0.0f, l1 = 0.0f;

    const float* mrow = mask + ((size_t)b * TSEQ + (t0 + w * 16 + (lane >> 2))) * TSEQ + 2 * (lane & 3);

    for (int it = 0; it < 32; ++it) {
        const int s0 = it * 64;
        const int cur = it & 1;
        asm volatile("cp.async.wait_group 0;");
        __syncthreads();
        if (it + 1 < 32) {
            const __half* kg = kbase + (size_t)(s0 + 64) * 64;
            const __half* vg = vbase + (size_t)(s0 + 64) * 64;
            const int nxt = cur ^ 1;
            for (int i = tid; i < 512; i += 128) {
                int r = i >> 3, c = i & 7;
                cpa16(&Ks[nxt][r][c * 8], kg + r * 64 + c * 8);
                cpa16(&Vs[nxt][r][c * 8], vg + r * 64 + c * 8);
            }
            asm volatile("cp.async.commit_group;");
        }

        // prefetch mask (row0 / row0+8, cols j*8 + 2*(lane&3))
        float2 mk0[8], mk1[8];
        #pragma unroll
        for (int j = 0; j < 8; j++) {
            mk0[j] = *(const float2*)(mrow + s0 + j * 8);
            mk1[j] = *(const float2*)(mrow + 8 * TSEQ + s0 + j * 8);
        }

        // S = Q @ K^T
        float Sa[8][4];
        #pragma unroll
        for (int j = 0; j < 8; j++) { Sa[j][0] = Sa[j][1] = Sa[j][2] = Sa[j][3] = 0.0f; }
        #pragma unroll
        for (int ng = 0; ng < 4; ng++) {
            #pragma unroll
            for (int kk = 0; kk < 4; kk++) {
                uint32_t k0, k1, k2, k3;
                ldsm4(k0, k1, k2, k3, &Ks[cur][ng * 16 + (lane & 15)][kk * 16 + 8 * (lane >> 4)]);
                mma16816(Sa[2 * ng],     qa[kk], k0, k2);
                mma16816(Sa[2 * ng + 1], qa[kk], k1, k3);
            }
        }

        // mask add + online softmax (all in registers; quads share rows)
        float mx0 = -1e30f, mx1 = -1e30f;
        #pragma unroll
        for (int j = 0; j < 8; j++) {
            Sa[j][0] += mk0[j].x; Sa[j][1] += mk0[j].y;
            Sa[j][2] += mk1[j].x; Sa[j][3] += mk1[j].y;
            mx0 = fmaxf(mx0, fmaxf(Sa[j][0], Sa[j][1]));
            mx1 = fmaxf(mx1, fmaxf(Sa[j][2], Sa[j][3]));
        }
        mx0 = fmaxf(mx0, __shfl_xor_sync(0xffffffffu, mx0, 1));
        mx0 = fmaxf(mx0, __shfl_xor_sync(0xffffffffu, mx0, 2));
        mx1 = fmaxf(mx1, __shfl_xor_sync(0xffffffffu, mx1, 1));
        mx1 = fmaxf(mx1, __shfl_xor_sync(0xffffffffu, mx1, 2));
        float mn0 = fmaxf(m0, mx0), mn1 = fmaxf(m1, mx1);
        float alpha0 = ex2((m0 - mn0) * LOG2E);
        float alpha1 = ex2((m1 - mn1) * LOG2E);
        m0 = mn0; m1 = mn1;

        float rs0 = 0.0f, rs1 = 0.0f;
        #pragma unroll
        for (int j = 0; j < 8; j++) {
            Sa[j][0] = ex2((Sa[j][0] - mn0) * LOG2E);
            Sa[j][1] = ex2((Sa[j][1] - mn0) * LOG2E);
            Sa[j][2] = ex2((Sa[j][2] - mn1) * LOG2E);
            Sa[j][3] = ex2((Sa[j][3] - mn1) * LOG2E);
            rs0 += Sa[j][0] + Sa[j][1];
            rs1 += Sa[j][2] + Sa[j][3];
        }
        rs0 += __shfl_xor_sync(0xffffffffu, rs0, 1);
        rs0 += __shfl_xor_sync(0xffffffffu, rs0, 2);
        rs1 += __shfl_xor_sync(0xffffffffu, rs1, 1);
        rs1 += __shfl_xor_sync(0xffffffffu, rs1, 2);
        l0 = l0 * alpha0 + rs0;
        l1 = l1 * alpha1 + rs1;

        // pack P fragments (C-layout of m16n8 == A-layout of m16n8k16)
        uint32_t Pa[4][4];
        #pragma unroll
        for (int kk = 0; kk < 4; kk++) {
            Pa[kk][0] = h2u(__floats2half2_rn(Sa[2 * kk][0],     Sa[2 * kk][1]));
            Pa[kk][1] = h2u(__floats2half2_rn(Sa[2 * kk][2],     Sa[2 * kk][3]));
            Pa[kk][2] = h2u(__floats2half2_rn(Sa[2 * kk + 1][0], Sa[2 * kk + 1][1]));
            Pa[kk][3] = h2u(__floats2half2_rn(Sa[2 * kk + 1][2], Sa[2 * kk + 1][3]));
        }

        // rescale O
        #pragma unroll
        for (int j = 0; j < 8; j++) {
            Oa[j][0] *= alpha0; Oa[j][1] *= alpha0;
            Oa[j][2] *= alpha1; Oa[j][3] *= alpha1;
        }

        // O += P @ V
        #pragma unroll
        for (int kk = 0; kk < 4; kk++) {
            #pragma unroll
            for (int ng = 0; ng < 4; ng++) {
                uint32_t v0, v1, v2, v3;
                ldsm4t(v0, v1, v2, v3,
                       &Vs[cur][kk * 16 + (lane & 7) + 8 * ((lane >> 3) & 1)][ng * 16 + 8 * (lane >> 4)]);
                mma16816(Oa[2 * ng],     Pa[kk], v0, v1);
                mma16816(Oa[2 * ng + 1], Pa[kk], v2, v3);
            }
        }
    }

    // epilogue: normalize + write [t*B+b][h*64+d]
    const float inv0 = 1.0f / l0, inv1 = 1.0f / l1;
    const int r0g = t0 + w * 16 + (lane >> 2);
    const int r1g = r0g + 8;
    #pragma unroll
    for (int j = 0; j < 8; j++) {
        int col = h * DH + j * 8 + 2 * (lane & 3);
        __half2* p0 = (__half2*)(g_ao + ((size_t)r0g * BATCH + b) * DMODEL + col);
        __half2* p1 = (__half2*)(g_ao + ((size_t)r1g * BATCH + b) * DMODEL + col);
        *p0 = __floats2half2_rn(Oa[j][0] * inv0, Oa[j][1] * inv0);
        *p1 = __floats2half2_rn(Oa[j][2] * inv1, Oa[j][3] * inv1);
    }
}

// =====================================================================
// Output projection: OUT[8192,64] = AO[8192,512] @ Wo + bo
// =====================================================================
__global__ __launch_bounds__(128) void oproj_kernel(const float* __restrict__ W,
                                                    const float* __restrict__ bias,
                                                    float* __restrict__ out) {
    __shared__ __half As[64][72];
    __shared__ __half Ws[64][72];
    __shared__ float  Cs[64][68];
    const int tid = threadIdx.x;
    const int m0 = blockIdx.x * 64;
    const int w = tid >> 5, wy = w >> 1, wx = w & 1;

    wmma::fragment<wmma::accumulator, 16, 16, 16, float> acc[2][2];
    for (int i = 0; i < 2; i++) for (int j = 0; j < 2; j++) wmma::fill_fragment(acc[i][j], 0.0f);

    for (int kc = 0; kc < DMODEL / 64; kc++) {
        for (int i = tid; i < 64 * 64; i += 128) {
            int r = i >> 6, c = i & 63;
            As[r][c] = g_ao[(size_t)(m0 + r) * DMODEL + kc * 64 + c];
            Ws[r][c] = __float2half(W[(size_t)(kc * 64 + r) * DH + c]);
        }
        __syncthreads();
        for (int k = 0; k < 4; k++) {
            wmma::fragment<wmma::matrix_a, 16, 16, 16, __half, wmma::row_major> a[2];
            for (int i = 0; i < 2; i++)
                wmma::load_matrix_sync(a[i], &As[wy * 32 + i * 16][k * 16], 72);
            for (int j = 0; j < 2; j++) {
                wmma::fragment<wmma::matrix_b, 16, 16, 16, __half, wmma::row_major> bf;
                wmma::load_matrix_sync(bf, &Ws[k * 16][wx * 32 + j * 16], 72);
                for (int i = 0; i < 2; i++) wmma::mma_sync(acc[i][j], a[i], bf, acc[i][j]);
            }
        }
        __syncthreads();
    }
    for (int i = 0; i < 2; i++)
        for (int j = 0; j < 2; j++)
            wmma::store_matrix_sync(&Cs[wy * 32 + i * 16][wx * 32 + j * 16], acc[i][j], 68, wmma::mem_row_major);
    __syncthreads();

    for (int i = tid; i < 64 * 64; i += 128) {
        int r = i >> 6, c = i & 63;
        out[(size_t)(m0 + r) * DH + c] = Cs[r][c] + bias[c];
    }
}

// =====================================================================
extern "C" void kernel_launch(void* const* d_in, const int* in_sizes, int n_in,
                              void* d_out, int out_size) {
    const float* query = (const float*)d_in[0];
    const float* key   = (const float*)d_in[1];
    const float* value = (const float*)d_in[2];
    const float* amask = (const float*)d_in[3];
    const float* Wq1 = (const float*)d_in[4];
    const float* bq1 = (const float*)d_in[5];
    const float* Wq2 = (const float*)d_in[6];
    const float* bq2 = (const float*)d_in[7];
    const float* Wk1 = (const float*)d_in[8];
    const float* bk1 = (const float*)d_in[9];
    const float* Wk2 = (const float*)d_in[10];
    const float* bk2 = (const float*)d_in[11];
    const float* Wv1 = (const float*)d_in[12];
    const float* bv1 = (const float*)d_in[13];
    const float* Wv2 = (const float*)d_in[14];
    const float* bv2 = (const float*)d_in[15];
    const float* Wo  = (const float*)d_in[16];
    const float* bo  = (const float*)d_in[17];
    float* out = (float*)d_out;

    dim3 blk(128);
    mlp1_kernel<<<dim3(HIDDEN / 64, NTOK / 64, 3), blk>>>(query, key, value,
                                                          Wq1, Wk1, Wv1, bq1, bk1, bv1);
    mlp2_kernel<<<dim3(DMODEL / 64, NTOK / 64, 3), blk>>>(Wq2, Wk2, Wv2, bq2, bk2, bv2);
    attn_kernel<<<dim3(NHEADS, TSEQ / 64, BATCH), blk>>>(amask);
    oproj_kernel<<<dim3(NTOK / 64), blk>>>(Wo, bo, out);
}

// round 5
// speedup vs baseline: 5.7165x; 1.3183x over previous
#include <cuda_runtime.h>
#include <cuda_fp16.h>
#include <cstdint>

#define NHEADS   8
#define DH       64
#define TSEQ     2048
#define BATCH    4
#define HIDDEN   256
#define DMODEL   (NHEADS * DH)      // 512
#define NTOK     (TSEQ * BATCH)     // 8192
#define SCALING  0.125f
#define LOG2E    1.4426950408889634f

// ---------------- device scratch ----------------
__device__ __half g_w1h[3][DH * HIDDEN];        // [64][256] row-major
__device__ __half g_w2h[3][HIDDEN * DMODEL];    // [256][512]
__device__ __half g_woh[DMODEL * DH];           // [512][64]
__device__ __half g_hid[3][NTOK * HIDDEN];
__device__ __half g_q[BATCH * NHEADS * TSEQ * DH];   // [b,h,t,d], q pre-scaled
__device__ __half g_k[BATCH * NHEADS * TSEQ * DH];
__device__ __half g_v[BATCH * NHEADS * TSEQ * DH];
__device__ __half g_ao[NTOK * DMODEL];               // [t*B+b][h*64+d]

// ======================= PTX helpers =======================
__device__ __forceinline__ void ldsm4(uint32_t& r0, uint32_t& r1, uint32_t& r2, uint32_t& r3, const void* p) {
    uint32_t a = (uint32_t)__cvta_generic_to_shared(p);
    asm volatile("ldmatrix.sync.aligned.m8n8.x4.shared.b16 {%0,%1,%2,%3}, [%4];"
                 : "=r"(r0), "=r"(r1), "=r"(r2), "=r"(r3) : "r"(a));
}
__device__ __forceinline__ void ldsm4t(uint32_t& r0, uint32_t& r1, uint32_t& r2, uint32_t& r3, const void* p) {
    uint32_t a = (uint32_t)__cvta_generic_to_shared(p);
    asm volatile("ldmatrix.sync.aligned.m8n8.x4.trans.shared.b16 {%0,%1,%2,%3}, [%4];"
                 : "=r"(r0), "=r"(r1), "=r"(r2), "=r"(r3) : "r"(a));
}
__device__ __forceinline__ void mma16816(float* c, const uint32_t* a, uint32_t b0, uint32_t b1) {
    asm volatile("mma.sync.aligned.m16n8k16.row.col.f32.f16.f16.f32 "
                 "{%0,%1,%2,%3}, {%4,%5,%6,%7}, {%8,%9}, {%0,%1,%2,%3};"
                 : "+f"(c[0]), "+f"(c[1]), "+f"(c[2]), "+f"(c[3])
                 : "r"(a[0]), "r"(a[1]), "r"(a[2]), "r"(a[3]), "r"(b0), "r"(b1));
}
__device__ __forceinline__ float ex2(float x) {
    float r; asm("ex2.approx.ftz.f32 %0, %1;" : "=f"(r) : "f"(x)); return r;
}
__device__ __forceinline__ void cpa16(void* dst, const void* src) {
    asm volatile("cp.async.cg.shared.global [%0], [%1], 16;"
                 :: "r"((uint32_t)__cvta_generic_to_shared(dst)), "l"(src));
}
__device__ __forceinline__ uint32_t h2u(__half2 v) {
    return *reinterpret_cast<uint32_t*>(&v);
}

// =====================================================================
// Weight pre-conversion (fp32 -> fp16), once per launch
// =====================================================================
__global__ __launch_bounds__(256) void convert_w_kernel(
        const float* __restrict__ Wq1, const float* __restrict__ Wk1, const float* __restrict__ Wv1,
        const float* __restrict__ Wq2, const float* __restrict__ Wk2, const float* __restrict__ Wv2,
        const float* __restrict__ Wo) {
    const int tid = blockIdx.x * blockDim.x + threadIdx.x;
    const int stride = gridDim.x * blockDim.x;
    const int N1 = DH * HIDDEN;        // 16384
    const int N2 = HIDDEN * DMODEL;    // 131072
    for (int i = tid; i < 3 * N1; i += stride) {
        int z = i / N1, j = i - z * N1;
        const float* s = (z == 0) ? Wq1 : (z == 1) ? Wk1 : Wv1;
        g_w1h[z][j] = __float2half(s[j]);
    }
    for (int i = tid; i < 3 * N2; i += stride) {
        int z = i / N2, j = i - z * N2;
        const float* s = (z == 0) ? Wq2 : (z == 1) ? Wk2 : Wv2;
        g_w2h[z][j] = __float2half(s[j]);
    }
    for (int i = tid; i < DMODEL * DH; i += stride)
        g_woh[i] = __float2half(Wo[i]);
}

// =====================================================================
// MLP stage 1: H = relu(X @ W1 + b1).  M-tile 128, N-tile 128, K=64.
// grid (2, 64, 3), 256 threads (8 warps: 4 m-strips x 2 n-chunks)
// =====================================================================
__global__ __launch_bounds__(256) void mlp1_kernel(
        const float* __restrict__ Xq, const float* __restrict__ Xk, const float* __restrict__ Xv,
        const float* __restrict__ bq, const float* __restrict__ bk, const float* __restrict__ bv) {
    __shared__ __half Xs[128][72];
    __shared__ __half Ws[2][64][72];
    const int tid = threadIdx.x, lane = tid & 31, w = tid >> 5;
    const int my = w & 3, wx = w >> 2;
    const int n0 = blockIdx.x * 128, m0 = blockIdx.y * 128, z = blockIdx.z;
    const float* X    = (z == 0) ? Xq : (z == 1) ? Xk : Xv;
    const float* bias = (z == 0) ? bq : (z == 1) ? bk : bv;

    for (int idx = tid; idx < 1024; idx += 256) {
        int r = idx >> 3, c8 = idx & 7;
        const float4* src = (const float4*)(X + (size_t)(m0 + r) * DH + c8 * 8);
        float4 f0 = src[0], f1 = src[1];
        uint4 u;
        u.x = h2u(__floats2half2_rn(f0.x, f0.y));
        u.y = h2u(__floats2half2_rn(f0.z, f0.w));
        u.z = h2u(__floats2half2_rn(f1.x, f1.y));
        u.w = h2u(__floats2half2_rn(f1.z, f1.w));
        *(uint4*)&Xs[r][c8 * 8] = u;
    }
    for (int idx = tid; idx < 1024; idx += 256) {
        int r = idx >> 4, c8 = idx & 15;
        *(uint4*)&Ws[c8 >> 3][r][(c8 & 7) * 8] =
            *(const uint4*)(g_w1h[z] + (size_t)r * HIDDEN + n0 + c8 * 8);
    }
    __syncthreads();

    float acc[2][8][4];
    #pragma unroll
    for (int i = 0; i < 2; i++)
        #pragma unroll
        for (int j = 0; j < 8; j++)
            acc[i][j][0] = acc[i][j][1] = acc[i][j][2] = acc[i][j][3] = 0.0f;

    #pragma unroll
    for (int kk = 0; kk < 4; kk++) {
        uint32_t a[2][4];
        #pragma unroll
        for (int i = 0; i < 2; i++)
            ldsm4(a[i][0], a[i][1], a[i][2], a[i][3],
                  &Xs[my * 32 + i * 16 + (lane & 15)][kk * 16 + 8 * (lane >> 4)]);
        #pragma unroll
        for (int ng = 0; ng < 4; ng++) {
            uint32_t v0, v1, v2, v3;
            ldsm4t(v0, v1, v2, v3,
                   &Ws[wx][kk * 16 + (lane & 7) + 8 * ((lane >> 3) & 1)][ng * 16 + 8 * (lane >> 4)]);
            #pragma unroll
            for (int i = 0; i < 2; i++) {
                mma16816(acc[i][2 * ng],     a[i], v0, v1);
                mma16816(acc[i][2 * ng + 1], a[i], v2, v3);
            }
        }
    }

    const int colbase = n0 + wx * 64;
    #pragma unroll
    for (int j = 0; j < 8; j++) {
        int col = colbase + j * 8 + 2 * (lane & 3);
        float b0 = bias[col], b1 = bias[col + 1];
        #pragma unroll
        for (int i = 0; i < 2; i++) {
            int row = m0 + my * 32 + i * 16 + (lane >> 2);
            *(__half2*)&g_hid[z][(size_t)row * HIDDEN + col] =
                __floats2half2_rn(fmaxf(acc[i][j][0] + b0, 0.f), fmaxf(acc[i][j][1] + b1, 0.f));
            *(__half2*)&g_hid[z][(size_t)(row + 8) * HIDDEN + col] =
                __floats2half2_rn(fmaxf(acc[i][j][2] + b0, 0.f), fmaxf(acc[i][j][3] + b1, 0.f));
        }
    }
}

// =====================================================================
// MLP stage 2: OUT = (H @ W2 + b2) * scale -> [b,h,t,d]
// M-tile 128, N-tile 128, K=256 (4 chunks, double-buffered cp.async).
// grid (4, 64, 3), 256 threads. Dynamic smem 73728 B.
// =====================================================================
__global__ __launch_bounds__(256) void mlp2_kernel(
        const float* __restrict__ bq, const float* __restrict__ bk, const float* __restrict__ bv) {
    extern __shared__ char dynsm[];
    __half (*As)[128][72]    = (__half(*)[128][72])dynsm;              // 2 x 18432 B
    __half (*Ws)[2][64][72]  = (__half(*)[2][64][72])(dynsm + 36864);  // 2 x 18432 B
    const int tid = threadIdx.x, lane = tid & 31, w = tid >> 5;
    const int my = w & 3, wx = w >> 2;
    const int nb = blockIdx.x, m0 = blockIdx.y * 128, z = blockIdx.z;
    const float* bias  = (z == 0) ? bq : (z == 1) ? bk : bv;
    const float scale  = (z == 0) ? SCALING : 1.0f;
    const __half* Hsrc = g_hid[z];
    const __half* Wsrc = g_w2h[z];
    const int n0 = nb * 128;

    auto issue = [&](int st, int kc) {
        for (int idx = tid; idx < 1024; idx += 256) {
            int r = idx >> 3, c8 = idx & 7;
            cpa16(&As[st][r][c8 * 8], Hsrc + (size_t)(m0 + r) * HIDDEN + kc * 64 + c8 * 8);
        }
        for (int idx = tid; idx < 1024; idx += 256) {
            int r = idx >> 4, c8 = idx & 15;
            cpa16(&Ws[st][c8 >> 3][r][(c8 & 7) * 8],
                  Wsrc + (size_t)(kc * 64 + r) * DMODEL + n0 + c8 * 8);
        }
        asm volatile("cp.async.commit_group;");
    };

    issue(0, 0);

    float acc[2][8][4];
    #pragma unroll
    for (int i = 0; i < 2; i++)
        #pragma unroll
        for (int j = 0; j < 8; j++)
            acc[i][j][0] = acc[i][j][1] = acc[i][j][2] = acc[i][j][3] = 0.0f;

    for (int kc = 0; kc < 4; kc++) {
        asm volatile("cp.async.wait_group 0;");
        __syncthreads();
        if (kc + 1 < 4) issue((kc + 1) & 1, kc + 1);
        const int cur = kc & 1;
        #pragma unroll
        for (int kk = 0; kk < 4; kk++) {
            uint32_t a[2][4];
            #pragma unroll
            for (int i = 0; i < 2; i++)
                ldsm4(a[i][0], a[i][1], a[i][2], a[i][3],
                      &As[cur][my * 32 + i * 16 + (lane & 15)][kk * 16 + 8 * (lane >> 4)]);
            #pragma unroll
            for (int ng = 0; ng < 4; ng++) {
                uint32_t v0, v1, v2, v3;
                ldsm4t(v0, v1, v2, v3,
                       &Ws[cur][wx][kk * 16 + (lane & 7) + 8 * ((lane >> 3) & 1)][ng * 16 + 8 * (lane >> 4)]);
                #pragma unroll
                for (int i = 0; i < 2; i++) {
                    mma16816(acc[i][2 * ng],     a[i], v0, v1);
                    mma16816(acc[i][2 * ng + 1], a[i], v2, v3);
                }
            }
        }
        __syncthreads();
    }

    __half* dst = (z == 0) ? g_q : (z == 1) ? g_k : g_v;
    const int colbase = n0 + wx * 64;
    #pragma unroll
    for (int j = 0; j < 8; j++) {
        int col = colbase + j * 8 + 2 * (lane & 3);
        float b0 = bias[col], b1 = bias[col + 1];
        int h = col >> 6, d = col & 63;
        #pragma unroll
        for (int i = 0; i < 2; i++) {
            #pragma unroll
            for (int half_ = 0; half_ < 2; half_++) {
                int row = m0 + my * 32 + i * 16 + (lane >> 2) + half_ * 8;
                int t = row >> 2, b = row & 3;
                float v0f = (acc[i][j][2 * half_]     + b0) * scale;
                float v1f = (acc[i][j][2 * half_ + 1] + b1) * scale;
                *(__half2*)&dst[(((size_t)(b * NHEADS + h)) * TSEQ + t) * DH + d] =
                    __floats2half2_rn(v0f, v1f);
            }
        }
    }
}

// =====================================================================
// Flash attention (unchanged from R4 — FA2 register pipeline)
// =====================================================================
__global__ __launch_bounds__(128, 3) void attn_kernel(const float* __restrict__ mask) {
    __shared__ __half Qs[64][72];
    __shared__ __half Ks[2][64][72];
    __shared__ __half Vs[2][64][72];

    const int tid  = threadIdx.x;
    const int lane = tid & 31;
    const int w    = tid >> 5;
    const int h    = blockIdx.x;
    const int t0   = blockIdx.y * 64;
    const int b    = blockIdx.z;

    const __half* qbase = g_q + ((size_t)(b * NHEADS + h) * TSEQ + t0) * DH;
    const __half* kbase = g_k + (size_t)(b * NHEADS + h) * TSEQ * DH;
    const __half* vbase = g_v + (size_t)(b * NHEADS + h) * TSEQ * DH;

    for (int i = tid; i < 64 * 8; i += 128) {
        int r = i >> 3, c = i & 7;
        *(uint4*)&Qs[r][c * 8] = ((const uint4*)qbase)[i];
    }
    for (int i = tid; i < 512; i += 128) {
        int r = i >> 3, c = i & 7;
        cpa16(&Ks[0][r][c * 8], kbase + r * 64 + c * 8);
        cpa16(&Vs[0][r][c * 8], vbase + r * 64 + c * 8);
    }
    asm volatile("cp.async.commit_group;");
    __syncthreads();

    uint32_t qa[4][4];
    #pragma unroll
    for (int kk = 0; kk < 4; kk++)
        ldsm4(qa[kk][0], qa[kk][1], qa[kk][2], qa[kk][3],
              &Qs[w * 16 + (lane & 15)][kk * 16 + 8 * (lane >> 4)]);

    float Oa[8][4];
    #pragma unroll
    for (int j = 0; j < 8; j++) { Oa[j][0] = Oa[j][1] = Oa[j][2] = Oa[j][3] = 0.0f; }
    float m0 = -1e30f, m1 = -1e30f, l0 = 0.0f, l1 = 0.0f;

    const float* mrow = mask + ((size_t)b * TSEQ + (t0 + w * 16 + (lane >> 2))) * TSEQ + 2 * (lane & 3);

    for (int it = 0; it < 32; ++it) {
        const int s0 = it * 64;
        const int cur = it & 1;
        asm volatile("cp.async.wait_group 0;");
        __syncthreads();
        if (it + 1 < 32) {
            const __half* kg = kbase + (size_t)(s0 + 64) * 64;
            const __half* vg = vbase + (size_t)(s0 + 64) * 64;
            const int nxt = cur ^ 1;
            for (int i = tid; i < 512; i += 128) {
                int r = i >> 3, c = i & 7;
                cpa16(&Ks[nxt][r][c * 8], kg + r * 64 + c * 8);
                cpa16(&Vs[nxt][r][c * 8], vg + r * 64 + c * 8);
            }
            asm volatile("cp.async.commit_group;");
        }

        float2 mk0[8], mk1[8];
        #pragma unroll
        for (int j = 0; j < 8; j++) {
            mk0[j] = *(const float2*)(mrow + s0 + j * 8);
            mk1[j] = *(const float2*)(mrow + 8 * TSEQ + s0 + j * 8);
        }

        float Sa[8][4];
        #pragma unroll
        for (int j = 0; j < 8; j++) { Sa[j][0] = Sa[j][1] = Sa[j][2] = Sa[j][3] = 0.0f; }
        #pragma unroll
        for (int ng = 0; ng < 4; ng++) {
            #pragma unroll
            for (int kk = 0; kk < 4; kk++) {
                uint32_t k0, k1, k2, k3;
                ldsm4(k0, k1, k2, k3, &Ks[cur][ng * 16 + (lane & 15)][kk * 16 + 8 * (lane >> 4)]);
                mma16816(Sa[2 * ng],     qa[kk], k0, k2);
                mma16816(Sa[2 * ng + 1], qa[kk], k1, k3);
            }
        }

        float mx0 = -1e30f, mx1 = -1e30f;
        #pragma unroll
        for (int j = 0; j < 8; j++) {
            Sa[j][0] += mk0[j].x; Sa[j][1] += mk0[j].y;
            Sa[j][2] += mk1[j].x; Sa[j][3] += mk1[j].y;
            mx0 = fmaxf(mx0, fmaxf(Sa[j][0], Sa[j][1]));
            mx1 = fmaxf(mx1, fmaxf(Sa[j][2], Sa[j][3]));
        }
        mx0 = fmaxf(mx0, __shfl_xor_sync(0xffffffffu, mx0, 1));
        mx0 = fmaxf(mx0, __shfl_xor_sync(0xffffffffu, mx0, 2));
        mx1 = fmaxf(mx1, __shfl_xor_sync(0xffffffffu, mx1, 1));
        mx1 = fmaxf(mx1, __shfl_xor_sync(0xffffffffu, mx1, 2));
        float mn0 = fmaxf(m0, mx0), mn1 = fmaxf(m1, mx1);
        float alpha0 = ex2((m0 - mn0) * LOG2E);
        float alpha1 = ex2((m1 - mn1) * LOG2E);
        m0 = mn0; m1 = mn1;

        float rs0 = 0.0f, rs1 = 0.0f;
        #pragma unroll
        for (int j = 0; j < 8; j++) {
            Sa[j][0] = ex2((Sa[j][0] - mn0) * LOG2E);
            Sa[j][1] = ex2((Sa[j][1] - mn0) * LOG2E);
            Sa[j][2] = ex2((Sa[j][2] - mn1) * LOG2E);
            Sa[j][3] = ex2((Sa[j][3] - mn1) * LOG2E);
            rs0 += Sa[j][0] + Sa[j][1];
            rs1 += Sa[j][2] + Sa[j][3];
        }
        rs0 += __shfl_xor_sync(0xffffffffu, rs0, 1);
        rs0 += __shfl_xor_sync(0xffffffffu, rs0, 2);
        rs1 += __shfl_xor_sync(0xffffffffu, rs1, 1);
        rs1 += __shfl_xor_sync(0xffffffffu, rs1, 2);
        l0 = l0 * alpha0 + rs0;
        l1 = l1 * alpha1 + rs1;

        uint32_t Pa[4][4];
        #pragma unroll
        for (int kk = 0; kk < 4; kk++) {
            Pa[kk][0] = h2u(__floats2half2_rn(Sa[2 * kk][0],     Sa[2 * kk][1]));
            Pa[kk][1] = h2u(__floats2half2_rn(Sa[2 * kk][2],     Sa[2 * kk][3]));
            Pa[kk][2] = h2u(__floats2half2_rn(Sa[2 * kk + 1][0], Sa[2 * kk + 1][1]));
            Pa[kk][3] = h2u(__floats2half2_rn(Sa[2 * kk + 1][2], Sa[2 * kk + 1][3]));
        }

        #pragma unroll
        for (int j = 0; j < 8; j++) {
            Oa[j][0] *= alpha0; Oa[j][1] *= alpha0;
            Oa[j][2] *= alpha1; Oa[j][3] *= alpha1;
        }

        #pragma unroll
        for (int kk = 0; kk < 4; kk++) {
            #pragma unroll
            for (int ng = 0; ng < 4; ng++) {
                uint32_t v0, v1, v2, v3;
                ldsm4t(v0, v1, v2, v3,
                       &Vs[cur][kk * 16 + (lane & 7) + 8 * ((lane >> 3) & 1)][ng * 16 + 8 * (lane >> 4)]);
                mma16816(Oa[2 * ng],     Pa[kk], v0, v1);
                mma16816(Oa[2 * ng + 1], Pa[kk], v2, v3);
            }
        }
    }

    const float inv0 = 1.0f / l0, inv1 = 1.0f / l1;
    const int r0g = t0 + w * 16 + (lane >> 2);
    const int r1g = r0g + 8;
    #pragma unroll
    for (int j = 0; j < 8; j++) {
        int col = h * DH + j * 8 + 2 * (lane & 3);
        __half2* p0 = (__half2*)(g_ao + ((size_t)r0g * BATCH + b) * DMODEL + col);
        __half2* p1 = (__half2*)(g_ao + ((size_t)r1g * BATCH + b) * DMODEL + col);
        *p0 = __floats2half2_rn(Oa[j][0] * inv0, Oa[j][1] * inv0);
        *p1 = __floats2half2_rn(Oa[j][2] * inv1, Oa[j][3] * inv1);
    }
}

// =====================================================================
// Output projection: OUT[8192,64] = AO[8192,512] @ Wo + bo  (fp32 out)
// M-tile 64, K=512 (8 chunks, double-buffered). grid 128, 256 threads
// (8 warps: 4 m-strips x 2 n-halves of 32)
// =====================================================================
__global__ __launch_bounds__(256) void oproj_kernel(const float* __restrict__ bias,
                                                    float* __restrict__ out) {
    __shared__ __half As[2][64][72];
    __shared__ __half Ws[2][64][72];
    const int tid = threadIdx.x, lane = tid & 31, w = tid >> 5;
    const int my = w & 3, wn = w >> 2;
    const int m0 = blockIdx.x * 64;

    auto issue = [&](int st, int kc) {
        for (int idx = tid; idx < 512; idx += 256) {
            int r = idx >> 3, c8 = idx & 7;
            cpa16(&As[st][r][c8 * 8], g_ao + (size_t)(m0 + r) * DMODEL + kc * 64 + c8 * 8);
        }
        for (int idx = tid; idx < 512; idx += 256) {
            int r = idx >> 3, c8 = idx & 7;
            cpa16(&Ws[st][r][c8 * 8], g_woh + (size_t)(kc * 64 + r) * DH + c8 * 8);
        }
        asm volatile("cp.async.commit_group;");
    };

    issue(0, 0);

    float acc[4][4];
    #pragma unroll
    for (int j = 0; j < 4; j++) acc[j][0] = acc[j][1] = acc[j][2] = acc[j][3] = 0.0f;

    for (int kc = 0; kc < 8; kc++) {
        asm volatile("cp.async.wait_group 0;");
        __syncthreads();
        if (kc + 1 < 8) issue((kc + 1) & 1, kc + 1);
        const int cur = kc & 1;
        #pragma unroll
        for (int kk = 0; kk < 4; kk++) {
            uint32_t a[4];
            ldsm4(a[0], a[1], a[2], a[3],
                  &As[cur][my * 16 + (lane & 15)][kk * 16 + 8 * (lane >> 4)]);
            #pragma unroll
            for (int ng = 0; ng < 2; ng++) {
                uint32_t v0, v1, v2, v3;
                ldsm4t(v0, v1, v2, v3,
                       &Ws[cur][kk * 16 + (lane & 7) + 8 * ((lane >> 3) & 1)][wn * 32 + ng * 16 + 8 * (lane >> 4)]);
                mma16816(acc[2 * ng],     a, v0, v1);
                mma16816(acc[2 * ng + 1], a, v2, v3);
            }
        }
        __syncthreads();
    }

    #pragma unroll
    for (int j = 0; j < 4; j++) {
        int col = wn * 32 + j * 8 + 2 * (lane & 3);
        float b0 = bias[col], b1 = bias[col + 1];
        int row = m0 + my * 16 + (lane >> 2);
        *(float2*)&out[(size_t)row * DH + col]       = make_float2(acc[j][0] + b0, acc[j][1] + b1);
        *(float2*)&out[(size_t)(row + 8) * DH + col] = make_float2(acc[j][2] + b0, acc[j][3] + b1);
    }
}

// =====================================================================
extern "C" void kernel_launch(void* const* d_in, const int* in_sizes, int n_in,
                              void* d_out, int out_size) {
    const float* query = (const float*)d_in[0];
    const float* key   = (const float*)d_in[1];
    const float* value = (const float*)d_in[2];
    const float* amask = (const float*)d_in[3];
    const float* Wq1 = (const float*)d_in[4];
    const float* bq1 = (const float*)d_in[5];
    const float* Wq2 = (const float*)d_in[6];
    const float* bq2 = (const float*)d_in[7];
    const float* Wk1 = (const float*)d_in[8];
    const float* bk1 = (const float*)d_in[9];
    const float* Wk2 = (const float*)d_in[10];
    const float* bk2 = (const float*)d_in[11];
    const float* Wv1 = (const float*)d_in[12];
    const float* bv1 = (const float*)d_in[13];
    const float* Wv2 = (const float*)d_in[14];
    const float* bv2 = (const float*)d_in[15];
    const float* Wo  = (const float*)d_in[16];
    const float* bo  = (const float*)d_in[17];
    float* out = (float*)d_out;

    convert_w_kernel<<<512, 256>>>(Wq1, Wk1, Wv1, Wq2, Wk2, Wv2, Wo);
    mlp1_kernel<<<dim3(2, 64, 3), 256>>>(query, key, value, bq1, bk1, bv1);
    cudaFuncSetAttribute(mlp2_kernel, cudaFuncAttributeMaxDynamicSharedMemorySize, 73728);
    mlp2_kernel<<<dim3(4, 64, 3), 256, 73728>>>(bq2, bk2, bv2);
    attn_kernel<<<dim3(NHEADS, TSEQ / 64, BATCH), 128>>>(amask);
    oproj_kernel<<<dim3(128), 256>>>(bo, out);
}